// round 13
// baseline (speedup 1.0000x reference)
#include <cuda_runtime.h>

// FeatureFuser: out = sigmoid( last-write-wins(sampling_map, refined[k] over window_k) )
// B=8, TOP_K=4, C=32, H=W=256, GRID=4 (cell 64x64), WINDOW=3 cells (192x192, clipped).
//
// Per output pixel exactly one source is read: refined[b, k_win, c, h, w] where
// k_win = max k whose window contains (h,w), else sampling_map[b,c,h,w].
//
// R13: single-wave persistent tiling + double-buffered TMA stores.
//  - grid = 1024 blocks <= 148 SM x 7 blocks -> exactly one wave (R12 ran 3.46
//    waves; each transition ~2360 cyc).
//  - each block processes NT=4 tiles (4096 floats each); region predicates and
//    base pointers amortized across tiles (bc invariant: 16 tiles per plane,
//    block's 4 tiles stay in one plane).
//  - two 16 KB staging buffers: tile t's TMA bulk store (evict_first) overlaps
//    tile t+1's loads+sigmoid; buffer reuse gated by cp.async.bulk.wait_group.read 1.
//  - loads keep R12's L2::evict_last policy (67 MB read set repeats per replay
//    and fits in 126 MB L2); writes keep evict_first (never re-read).
//
// w4 = tid & 63 invariant per thread -> x-predicates and base pointers hoisted.
// regions arrive as int32 (JAX x64 disabled downcasts the int64 request).

#define B_      8
#define K_      4
#define C_      32
#define H_      256
#define W_      256
#define W4_     (W_/4)
#define PLANE4  (H_*W_/4)      // 16384 float4s per (b,c) plane
#define V_      4              // float4s per thread per tile
#define NT_     4              // tiles per block
#define TILE4_  (256*V_)       // 1024 float4s per tile

__device__ __forceinline__ float fast_sigmoid(float x) {
    float t;
    asm("tanh.approx.f32 %0, %1;" : "=f"(t) : "f"(0.5f * x));
    return fmaf(0.5f, t, 0.5f);
}

__device__ __forceinline__ float4 ldg_evict_last(const float4* p, unsigned long long pol) {
    float4 v;
    asm volatile("ld.global.nc.L2::cache_hint.v4.f32 {%0,%1,%2,%3}, [%4], %5;"
                 : "=f"(v.x), "=f"(v.y), "=f"(v.z), "=f"(v.w)
                 : "l"(p), "l"(pol));
    return v;
}

__global__ void __launch_bounds__(256, 7)
feature_fuser_kernel(const float* __restrict__ smap,
                     const float* __restrict__ rmap,
                     const int* __restrict__ regions,
                     float* __restrict__ out)
{
    __shared__ float4 stage[2][TILE4_];              // 2 x 16 KB double buffer

    const int tid = threadIdx.x;
    const int w4  = tid & (W4_ - 1);                 // invariant per thread
    const int tile0 = blockIdx.x * NT_;              // first tile index
    const int bc = tile0 >> 4;                       // 16 tiles per (b,c) plane
    const int c  = bc & (C_ - 1);
    const int b  = bc >> 5;

    unsigned long long pol_last, pol_first;
    asm volatile("createpolicy.fractional.L2::evict_last.b64 %0, 1.0;"  : "=l"(pol_last));
    asm volatile("createpolicy.fractional.L2::evict_first.b64 %0, 1.0;" : "=l"(pol_first));

    // Hoisted per-k state: y-range and x-predicate (x fixed per thread).
    int ys[K_]; unsigned ylen[K_]; bool xok[K_];
    #pragma unroll
    for (int k = 0; k < K_; ++k) {
        ys[k]   = __ldg(&regions[(b * K_ + k) * 2 + 0]) << 6;
        int xs4 =  __ldg(&regions[(b * K_ + k) * 2 + 1]) << 4;   // float4 units
        ylen[k] = (unsigned)(min(ys[k] + 192, H_) - ys[k]);
        xok[k]  = (unsigned)(w4 - xs4) < (unsigned)(min(xs4 + 48, W4_) - xs4);
    }

    // Per-k source base pointers with w4 folded in.
    const float4* s4 = reinterpret_cast<const float4*>(smap) + (size_t)bc * PLANE4 + w4;
    const float4* r4 = reinterpret_cast<const float4*>(rmap)
                     + ((size_t)(b * K_) * C_ + c) * PLANE4 + w4;

    #pragma unroll
    for (int t = 0; t < NT_; ++t) {
        const int tileIdx = tile0 + t;
        const int hbase = ((tileIdx * 16) & (H_ - 1)) + (tid >> 6);

        // Gather + sigmoid into registers (no SMEM touched yet).
        float4 v[V_];
        #pragma unroll
        for (int i = 0; i < V_; ++i) {
            int h = hbase + 4 * i;
            const float4* p = s4;
            #pragma unroll
            for (int k = 0; k < K_; ++k) {           // ascending: last write wins
                bool inside = xok[k] & ((unsigned)(h - ys[k]) < ylen[k]);
                const float4* pk = r4 + (size_t)k * (C_ * PLANE4);
                p = inside ? pk : p;
            }
            v[i] = ldg_evict_last(p + h * W4_, pol_last);
        }
        #pragma unroll
        for (int i = 0; i < V_; ++i) {
            v[i].x = fast_sigmoid(v[i].x);
            v[i].y = fast_sigmoid(v[i].y);
            v[i].z = fast_sigmoid(v[i].z);
            v[i].w = fast_sigmoid(v[i].w);
        }

        // Buffer reuse gate: the TMA store issued for tile t-2 must have
        // finished READING stage[t&1] (<=1 outstanding group after the wait).
        if (t >= 2) {
            if (tid == 0)
                asm volatile("cp.async.bulk.wait_group.read 1;" ::: "memory");
            __syncthreads();
        }

        float4* buf = stage[t & 1];
        #pragma unroll
        for (int i = 0; i < V_; ++i)
            buf[i * 256 + tid] = v[i];               // STS.128, conflict-free

        __syncthreads();
        asm volatile("fence.proxy.async.shared::cta;" ::: "memory");
        if (tid == 0) {
            unsigned s = (unsigned)__cvta_generic_to_shared(buf);
            const float4* dst = reinterpret_cast<const float4*>(out)
                              + (size_t)tileIdx * TILE4_;
            asm volatile(
                "cp.async.bulk.global.shared::cta.bulk_group.L2::cache_hint [%0], [%1], %2, %3;\n\t"
                "cp.async.bulk.commit_group;\n\t"
                :: "l"(dst), "r"(s), "r"(TILE4_ * 16), "l"(pol_first) : "memory");
        }
        // No wait here: store overlaps the next tile's loads/compute.
    }

    // Block must stay alive until the TMA engine finishes reading SMEM.
    if (tid == 0)
        asm volatile("cp.async.bulk.wait_group.read 0;" ::: "memory");
}

extern "C" void kernel_launch(void* const* d_in, const int* in_sizes, int n_in,
                              void* d_out, int out_size)
{
    const float* smap    = (const float*)d_in[0];
    const float* rmap    = (const float*)d_in[1];
    const int*   regions = (const int*)d_in[2];
    float*       out     = (float*)d_out;

    const int total4  = B_ * C_ * H_ * W_ / 4;       // 4,194,304 float4s
    const int threads = 256;
    const int blocks  = total4 / (threads * V_ * NT_);   // 1024 -> single wave
    feature_fuser_kernel<<<blocks, threads>>>(smap, rmap, regions, out);
}

// round 14
// speedup vs baseline: 1.3361x; 1.3361x over previous
#include <cuda_runtime.h>

// FeatureFuser: out = sigmoid( last-write-wins(sampling_map, refined[k] over window_k) )
// B=8, TOP_K=4, C=32, H=W=256, GRID=4 (cell 64x64), WINDOW=3 cells (192x192, clipped).
//
// Per output pixel exactly one source is read: refined[b, k_win, c, h, w] where
// k_win = max k whose window contains (h,w), else sampling_map[b,c,h,w].
//
// R14 = R12 with 128-thread blocks: same per-thread shape (V_=4 float4s,
// warp-strided, regs<=32), but half the BAR domain and ~2x blocks/SM, so the
// per-block store tail (BAR -> fence -> 1-thread TMA issue) overlaps other
// blocks' compute instead of idling 8 warps. R13 showed persistence/smem-heavy
// variants lose on occupancy; this keeps the R12 structure intact.
//
// Policies (both proven individually):
//  - loads: ld.global.nc + L2::evict_last (67 MB read set repeats per graph
//    replay and fits in 126 MB L2)
//  - store: cp.async.bulk (TMA) + L2::evict_first (output never re-read)
//
// w4 = tid & 63 invariant per thread -> x-predicates and base pointers hoisted.
// regions arrive as int32 (JAX x64 disabled downcasts the int64 request).

#define B_      8
#define K_      4
#define C_      32
#define H_      256
#define W_      256
#define W4_     (W_/4)
#define PLANE4  (H_*W_/4)      // 16384 float4s per (b,c) plane
#define THREADS 128
#define V_      4              // float4s per thread, warp-strided
#define TILE4_  (THREADS*V_)   // 512 float4s per block

__device__ __forceinline__ float fast_sigmoid(float x) {
    float t;
    asm("tanh.approx.f32 %0, %1;" : "=f"(t) : "f"(0.5f * x));
    return fmaf(0.5f, t, 0.5f);
}

__device__ __forceinline__ float4 ldg_evict_last(const float4* p, unsigned long long pol) {
    float4 v;
    asm volatile("ld.global.nc.L2::cache_hint.v4.f32 {%0,%1,%2,%3}, [%4], %5;"
                 : "=f"(v.x), "=f"(v.y), "=f"(v.z), "=f"(v.w)
                 : "l"(p), "l"(pol));
    return v;
}

__global__ void __launch_bounds__(THREADS, 16)
feature_fuser_kernel(const float* __restrict__ smap,
                     const float* __restrict__ rmap,
                     const int* __restrict__ regions,
                     float* __restrict__ out)
{
    __shared__ float4 stage[TILE4_];                 // 8 KB output staging

    const int tid = threadIdx.x;
    const int w4  = tid & (W4_ - 1);                 // invariant per thread
    const int blockBase = blockIdx.x * TILE4_;       // float4 index
    const int bc = blockBase >> 14;                  // uniform per block (32 blocks/plane)
    const int c  = bc & (C_ - 1);
    const int b  = bc >> 5;
    const int hbase = ((blockBase >> 6) & (H_ - 1)) + (tid >> 6);   // + {0,1}

    unsigned long long pol_last, pol_first;
    asm volatile("createpolicy.fractional.L2::evict_last.b64 %0, 1.0;"  : "=l"(pol_last));
    asm volatile("createpolicy.fractional.L2::evict_first.b64 %0, 1.0;" : "=l"(pol_first));

    // Hoisted per-k state: y-range and x-predicate (x fixed per thread).
    int ys[K_]; unsigned ylen[K_]; bool xok[K_];
    #pragma unroll
    for (int k = 0; k < K_; ++k) {
        ys[k]   = __ldg(&regions[(b * K_ + k) * 2 + 0]) << 6;
        int xs4 =  __ldg(&regions[(b * K_ + k) * 2 + 1]) << 4;   // float4 units
        ylen[k] = (unsigned)(min(ys[k] + 192, H_) - ys[k]);
        xok[k]  = (unsigned)(w4 - xs4) < (unsigned)(min(xs4 + 48, W4_) - xs4);
    }

    // Per-k source base pointers with w4 folded in.
    const float4* s4 = reinterpret_cast<const float4*>(smap) + (size_t)bc * PLANE4 + w4;
    const float4* r4 = reinterpret_cast<const float4*>(rmap)
                     + ((size_t)(b * K_) * C_ + c) * PLANE4 + w4;

    float4 v[V_];
    #pragma unroll
    for (int i = 0; i < V_; ++i) {
        int h = hbase + 2 * i;                       // 128 threads cover 2 rows/iter
        const float4* p = s4;
        #pragma unroll
        for (int k = 0; k < K_; ++k) {               // ascending: last write wins
            bool inside = xok[k] & ((unsigned)(h - ys[k]) < ylen[k]);
            const float4* pk = r4 + (size_t)k * (C_ * PLANE4);
            p = inside ? pk : p;
        }
        v[i] = ldg_evict_last(p + h * W4_, pol_last);   // MLP=4, front-batched
    }

    #pragma unroll
    for (int i = 0; i < V_; ++i) {
        v[i].x = fast_sigmoid(v[i].x);
        v[i].y = fast_sigmoid(v[i].y);
        v[i].z = fast_sigmoid(v[i].z);
        v[i].w = fast_sigmoid(v[i].w);
        stage[i * THREADS + tid] = v[i];             // STS.128, conflict-free
    }

    // Publish SMEM to the async proxy, one elected thread bulk-stores 8 KB.
    __syncthreads();
    asm volatile("fence.proxy.async.shared::cta;" ::: "memory");
    if (tid == 0) {
        unsigned s = (unsigned)__cvta_generic_to_shared(stage);
        const float4* dst = reinterpret_cast<const float4*>(out) + blockBase;
        asm volatile(
            "cp.async.bulk.global.shared::cta.bulk_group.L2::cache_hint [%0], [%1], %2, %3;\n\t"
            "cp.async.bulk.commit_group;\n\t"
            "cp.async.bulk.wait_group.read 0;\n\t"
            :: "l"(dst), "r"(s), "r"(TILE4_ * 16), "l"(pol_first) : "memory");
    }
    // Other threads exit; the block (and its SMEM) stays alive until tid 0's
    // wait completes, so the TMA read of `stage` is safe.
}

extern "C" void kernel_launch(void* const* d_in, const int* in_sizes, int n_in,
                              void* d_out, int out_size)
{
    const float* smap    = (const float*)d_in[0];
    const float* rmap    = (const float*)d_in[1];
    const int*   regions = (const int*)d_in[2];
    float*       out     = (float*)d_out;

    const int total4 = B_ * C_ * H_ * W_ / 4;        // 4,194,304 float4s
    const int blocks = total4 / TILE4_;              // 8192
    feature_fuser_kernel<<<blocks, THREADS>>>(smap, rmap, regions, out);
}